// round 7
// baseline (speedup 1.0000x reference)
#include <cuda_runtime.h>
#include <cuda_fp16.h>

#define Bdim 2
#define Sdim 512
#define Fdim 16384
#define Ddim 768
#define Mdim 262144
#define BS   (Bdim * Sdim)       // 1024
#define D4   (Ddim / 4)          // 192

// -------- device scratch (static, no allocation) --------
__device__ uint2  g_Uth[(size_t)Fdim * 192];    // up_decoder^T [F, 768] fp16, 24 MB
__device__ uint2  g_Xh[(size_t)Fdim * 256];     // up_facts^T   [F,1024] fp16, 32 MB
__device__ float  g_vals[Mdim];
__device__ int    g_ii[Mdim];
__device__ int    g_jj[Mdim];
__device__ int    g_rowptr[Fdim + 1];
__device__ int    g_is64;

// -------- dtype detection: int64 vs int32 indices --------
__global__ void k_detect(const long long* __restrict__ ip) {
    long long v = ip[65536];
    g_is64 = (v >= 0 && v < (long long)Fdim) ? 1 : 0;
}

__global__ void k_convert(const void* __restrict__ ip, const void* __restrict__ jp) {
    int m = blockIdx.x * blockDim.x + threadIdx.x;
    if (m >= Mdim) return;
    if (g_is64) {
        g_ii[m] = (int)((const long long*)ip)[m];
        g_jj[m] = (int)((const long long*)jp)[m];
    } else {
        g_ii[m] = ((const int*)ip)[m];
        g_jj[m] = ((const int*)jp)[m];
    }
}

// -------- CSR row pointers via binary search on sorted i --------
__global__ void k_rowptr() {
    int r = blockIdx.x * blockDim.x + threadIdx.x;
    if (r > Fdim) return;
    int lo = 0, hi = Mdim;
    while (lo < hi) {
        int mid = (lo + hi) >> 1;
        if (g_ii[mid] < r) lo = mid + 1; else hi = mid;
    }
    g_rowptr[r] = lo;
}

// -------- fused transpose + fp32->fp16, 64x64 tiles, half2-packed smem ----
__device__ __forceinline__ void trans_h2_tile(const float* __restrict__ src,
                                              uint* __restrict__ dst,
                                              int nrows, int bx, int by) {
    __shared__ uint tile[64][33];
    int t   = threadIdx.x;
    int c   = t & 63;
    int rp0 = t >> 6;                // 0..3
#pragma unroll
    for (int it = 0; it < 8; it++) {
        int rp = rp0 + it * 4;       // 0..31 row-pair
        int r  = by + 2 * rp;
        float a = src[(size_t)r * Fdim + bx + c];
        float b = src[(size_t)(r + 1) * Fdim + bx + c];
        __half2 h = __floats2half2_rn(a, b);
        tile[c][rp] = *(uint*)&h;
    }
    __syncthreads();
    int lane = t & 31;
    int f0   = t >> 5;               // 0..7
    int rowu = nrows >> 1;           // uints per dst row
#pragma unroll
    for (int it = 0; it < 8; it++) {
        int f = f0 + it * 8;
        dst[(size_t)(bx + f) * rowu + (by >> 1) + lane] = tile[f][lane];
    }
}

// Single launch does both transposes: grid (256, 28); y<12 -> U, else X.
__global__ void __launch_bounds__(256) k_trans(const float* __restrict__ U,
                                               const float* __restrict__ X) {
    int bx = blockIdx.x * 64;
    int y  = blockIdx.y;
    if (y < 12) trans_h2_tile(U, (uint*)g_Uth, Ddim, bx, y * 64);
    else        trans_h2_tile(X, (uint*)g_Xh,  BS,  bx, (y - 12) * 64);
}

// -------- accumulate helper --------
__device__ __forceinline__ void acc_px(float4& a, float v, uint2 px) {
    float2 lo = __half22float2(*(const __half2*)&px.x);
    float2 hi = __half22float2(*(const __half2*)&px.y);
    a.x += v * lo.x; a.y += v * lo.y;
    a.z += v * hi.x; a.w += v * hi.y;
}

// -------- fused values + SpMM + output transpose --------
// Block owns 8 rows. Phase 1: cache 8 Dn rows in smem; warp w computes row w's
// connection values (dot of smem Dn row vs fp16 Uth[j] gather) -> g_vals.
// __syncthreads makes the global writes block-visible. Phase 2: panel SpMM
// with MLP-4 Xh gathers, epilogue transposes via padded smem stage.
#define SR 8
__global__ void __launch_bounds__(256) k_fused(const float* __restrict__ Dn,
                                               float* __restrict__ out) {
    __shared__ float4 sD[SR][192];      // 24 KB
    __shared__ float  stage[SR][1028];  // 32.9 KB
    int t  = threadIdx.x;
    int r0 = blockIdx.x * SR;
    int wid = t >> 5, lane = t & 31;

    // ---- load 8 Dn rows (1536 float4, 6 per thread, coalesced) ----
    const float4* __restrict__ Dp = (const float4*)Dn + (size_t)r0 * D4;
#pragma unroll
    for (int it = 0; it < 6; it++) {
        int idx = it * 256 + t;          // 0..1535
        ((float4*)sD)[idx] = Dp[idx];
    }
    __syncthreads();

    // ---- phase 1: values for this block's 8 rows (warp w -> row r0+w) ----
    {
        int r  = r0 + wid;
        int mb = g_rowptr[r], me = g_rowptr[r + 1];
        for (int m = mb; m < me; ++m) {
            int j = g_jj[m];
            const uint2* __restrict__ Ur = g_Uth + (size_t)j * 192;
            float s = 0.f;
#pragma unroll
            for (int k = 0; k < 6; k++) {
                int idx = k * 32 + lane;
                uint2  u = Ur[idx];
                float4 d = sD[wid][idx];
                float2 lo = __half22float2(*(const __half2*)&u.x);
                float2 hi = __half22float2(*(const __half2*)&u.y);
                s += d.x * lo.x + d.y * lo.y + d.z * hi.x + d.w * hi.y;
            }
#pragma unroll
            for (int o = 16; o > 0; o >>= 1) s += __shfl_xor_sync(0xffffffffu, s, o);
            if (lane == 0) g_vals[m] = s;
        }
    }
    __syncthreads();   // g_vals writes visible block-wide

    // ---- phase 2: SpMM over the 1024-col panel ----
#pragma unroll 1
    for (int rr = 0; rr < SR; rr++) {
        int r  = r0 + rr;
        int m  = g_rowptr[r], me = g_rowptr[r + 1];
        float4 a = make_float4(0.f, 0.f, 0.f, 0.f);

        for (; m + 4 <= me; m += 4) {
            int   j0 = g_jj[m],     j1 = g_jj[m + 1];
            int   j2 = g_jj[m + 2], j3 = g_jj[m + 3];
            float v0 = g_vals[m],     v1 = g_vals[m + 1];
            float v2 = g_vals[m + 2], v3 = g_vals[m + 3];
            uint2 x0 = g_Xh[(size_t)j0 * 256 + t];
            uint2 x1 = g_Xh[(size_t)j1 * 256 + t];
            uint2 x2 = g_Xh[(size_t)j2 * 256 + t];
            uint2 x3 = g_Xh[(size_t)j3 * 256 + t];
            acc_px(a, v0, x0); acc_px(a, v1, x1);
            acc_px(a, v2, x2); acc_px(a, v3, x3);
        }
        for (; m < me; ++m) {
            int   j = g_jj[m];
            float v = g_vals[m];
            uint2 x = g_Xh[(size_t)j * 256 + t];
            acc_px(a, v, x);
        }
        *(float4*)&stage[rr][4 * t] = a;
    }
    __syncthreads();

#pragma unroll
    for (int it = 0; it < 8; it++) {
        int g  = it * 256 + t;
        int c  = g & 1;
        int bs = g >> 1;
        float4 o;
        o.x = stage[4 * c + 0][bs];
        o.y = stage[4 * c + 1][bs];
        o.z = stage[4 * c + 2][bs];
        o.w = stage[4 * c + 3][bs];
        *(float4*)&out[(size_t)bs * Fdim + r0 + 4 * c] = o;
    }
}

extern "C" void kernel_launch(void* const* d_in, const int* in_sizes, int n_in,
                              void* d_out, int out_size) {
    const float* up_facts = (const float*)d_in[0];   // [B, S, F] fp32
    const float* down_enc = (const float*)d_in[1];   // [F, D]    fp32
    const float* up_dec   = (const float*)d_in[2];   // [D, F]    fp32
    const void*  iI       = d_in[3];                 // [M] int64 (or int32)
    const void*  jI       = d_in[4];                 // [M] int64 (or int32)
    float*       out      = (float*)d_out;           // [B, S, F] fp32

    k_detect<<<1, 1>>>((const long long*)iI);
    k_convert<<<Mdim / 256, 256>>>(iI, jI);

    k_trans<<<dim3(Fdim / 64, 12 + BS / 64), 256>>>(up_dec, up_facts);

    k_rowptr<<<(Fdim + 256) / 256, 256>>>();

    k_fused<<<Fdim / SR, 256>>>(down_enc, out);
}

// round 8
// speedup vs baseline: 1.3031x; 1.3031x over previous
#include <cuda_runtime.h>
#include <cuda_fp16.h>

#define Bdim 2
#define Sdim 512
#define Fdim 16384
#define Ddim 768
#define Mdim 262144
#define BS   (Bdim * Sdim)       // 1024
#define D4   (Ddim / 4)          // 192

// -------- device scratch (static, no allocation) --------
__device__ uint2  g_Uth[(size_t)Fdim * 192];    // up_decoder^T [F, 768] fp16, 24 MB
__device__ uint2  g_Xh[(size_t)Fdim * 256];     // up_facts^T   [F,1024] fp16, 32 MB
__device__ float  g_vals[Mdim];
__device__ int    g_ii[Mdim];
__device__ int    g_jj[Mdim];
__device__ int    g_rowptr[Fdim + 1];

// -------- index convert, dtype detected inline (broadcast load) --------
// i_indices sorted in [0,F). int64-index 65536 (byte 512KB) is in-bounds for
// both layouts; a true int64 value is < F, an int32-pair reinterpretation >= 2^32.
__global__ void k_convert(const void* __restrict__ ip, const void* __restrict__ jp) {
    long long probe = ((const long long*)ip)[65536];
    bool is64 = (probe >= 0 && probe < (long long)Fdim);
    int m = blockIdx.x * blockDim.x + threadIdx.x;
    if (m >= Mdim) return;
    if (is64) {
        g_ii[m] = (int)((const long long*)ip)[m];
        g_jj[m] = (int)((const long long*)jp)[m];
    } else {
        g_ii[m] = ((const int*)ip)[m];
        g_jj[m] = ((const int*)jp)[m];
    }
}

// -------- CSR row pointers via boundary scatter (i sorted) --------
// rowptr[r] = first m with ii[m] >= r. Thread m writes r in (ii[m-1], ii[m]].
__global__ void k_rowptr() {
    int m = blockIdx.x * blockDim.x + threadIdx.x;
    if (m >= Mdim) return;
    int cur  = g_ii[m];
    int prev = (m == 0) ? -1 : g_ii[m - 1];
    for (int r = prev + 1; r <= cur; ++r) g_rowptr[r] = m;
    if (m == Mdim - 1)
        for (int r = cur + 1; r <= Fdim; ++r) g_rowptr[r] = Mdim;
}

// -------- fused transpose + fp32->fp16, 64x64 tiles, half2-packed smem ----
__device__ __forceinline__ void trans_h2_tile(const float* __restrict__ src,
                                              uint* __restrict__ dst,
                                              int nrows, int bx, int by) {
    __shared__ uint tile[64][33];
    int t   = threadIdx.x;
    int c   = t & 63;
    int rp0 = t >> 6;                // 0..3
#pragma unroll
    for (int it = 0; it < 8; it++) {
        int rp = rp0 + it * 4;       // 0..31 row-pair
        int r  = by + 2 * rp;
        float a = src[(size_t)r * Fdim + bx + c];
        float b = src[(size_t)(r + 1) * Fdim + bx + c];
        __half2 h = __floats2half2_rn(a, b);
        tile[c][rp] = *(uint*)&h;
    }
    __syncthreads();
    int lane = t & 31;
    int f0   = t >> 5;               // 0..7
    int rowu = nrows >> 1;           // uints per dst row
#pragma unroll
    for (int it = 0; it < 8; it++) {
        int f = f0 + it * 8;
        dst[(size_t)(bx + f) * rowu + (by >> 1) + lane] = tile[f][lane];
    }
}

// Single launch does both transposes: grid (256, 28); y<12 -> U, else X.
__global__ void __launch_bounds__(256) k_trans(const float* __restrict__ U,
                                               const float* __restrict__ X) {
    int bx = blockIdx.x * 64;
    int y  = blockIdx.y;
    if (y < 12) trans_h2_tile(U, (uint*)g_Uth, Ddim, bx, y * 64);
    else        trans_h2_tile(X, (uint*)g_Xh,  BS,  bx, (y - 12) * 64);
}

// -------- values: one block per row i. Dn[i] (fp32) cached in smem; each
// warp computes one connection's dot against Ut_h[j] (fp16). --------
__global__ void __launch_bounds__(128) k_values(const float* __restrict__ Dn) {
    __shared__ float4 sD[192];          // Dn[i] as 192 float4 (3 KB)
    int i    = blockIdx.x;
    int t    = threadIdx.x;
    int wid  = t >> 5, lane = t & 31;

    const float4* __restrict__ Dr = (const float4*)Dn + (size_t)i * D4;
    if (t < 192) sD[t] = Dr[t];
    if (t + 128 < 192) sD[t + 128] = Dr[t + 128];
    __syncthreads();

    int mb = g_rowptr[i], me = g_rowptr[i + 1];
    for (int m = mb + wid; m < me; m += 4) {
        int j = g_jj[m];
        const uint2* __restrict__ Ur = g_Uth + (size_t)j * 192;
        float s = 0.f;
#pragma unroll
        for (int k = 0; k < 6; k++) {
            int idx = k * 32 + lane;
            uint2  u = Ur[idx];
            float4 d = sD[idx];
            float2 lo = __half22float2(*(const __half2*)&u.x);
            float2 hi = __half22float2(*(const __half2*)&u.y);
            s += d.x * lo.x + d.y * lo.y + d.z * hi.x + d.w * hi.y;
        }
#pragma unroll
        for (int o = 16; o > 0; o >>= 1) s += __shfl_xor_sync(0xffffffffu, s, o);
        if (lane == 0) g_vals[m] = s;
    }
}

// -------- accumulate helper --------
__device__ __forceinline__ void acc_px(float4& a, float v, uint2 px) {
    float2 lo = __half22float2(*(const __half2*)&px.x);
    float2 hi = __half22float2(*(const __half2*)&px.y);
    a.x += v * lo.x; a.y += v * lo.y;
    a.z += v * hi.x; a.w += v * hi.y;
}

// -------- fused SpMM + output transpose, MLP-4 gather batches --------
#define SR 8
__global__ void __launch_bounds__(256) k_spmm(float* __restrict__ out) {
    __shared__ float stage[SR][1028];
    int t  = threadIdx.x;
    int r0 = blockIdx.x * SR;

#pragma unroll 1
    for (int rr = 0; rr < SR; rr++) {
        int r  = r0 + rr;
        int m  = g_rowptr[r], me = g_rowptr[r + 1];
        float4 a = make_float4(0.f, 0.f, 0.f, 0.f);

        for (; m + 4 <= me; m += 4) {
            int   j0 = g_jj[m],     j1 = g_jj[m + 1];
            int   j2 = g_jj[m + 2], j3 = g_jj[m + 3];
            float v0 = g_vals[m],     v1 = g_vals[m + 1];
            float v2 = g_vals[m + 2], v3 = g_vals[m + 3];
            uint2 x0 = g_Xh[(size_t)j0 * 256 + t];
            uint2 x1 = g_Xh[(size_t)j1 * 256 + t];
            uint2 x2 = g_Xh[(size_t)j2 * 256 + t];
            uint2 x3 = g_Xh[(size_t)j3 * 256 + t];
            acc_px(a, v0, x0); acc_px(a, v1, x1);
            acc_px(a, v2, x2); acc_px(a, v3, x3);
        }
        for (; m < me; ++m) {
            int   j = g_jj[m];
            float v = g_vals[m];
            uint2 x = g_Xh[(size_t)j * 256 + t];
            acc_px(a, v, x);
        }
        *(float4*)&stage[rr][4 * t] = a;
    }
    __syncthreads();

#pragma unroll
    for (int it = 0; it < 8; it++) {
        int g  = it * 256 + t;
        int c  = g & 1;
        int bs = g >> 1;
        float4 o;
        o.x = stage[4 * c + 0][bs];
        o.y = stage[4 * c + 1][bs];
        o.z = stage[4 * c + 2][bs];
        o.w = stage[4 * c + 3][bs];
        *(float4*)&out[(size_t)bs * Fdim + r0 + 4 * c] = o;
    }
}

extern "C" void kernel_launch(void* const* d_in, const int* in_sizes, int n_in,
                              void* d_out, int out_size) {
    const float* up_facts = (const float*)d_in[0];   // [B, S, F] fp32
    const float* down_enc = (const float*)d_in[1];   // [F, D]    fp32
    const float* up_dec   = (const float*)d_in[2];   // [D, F]    fp32
    const void*  iI       = d_in[3];                 // [M] int64 (or int32)
    const void*  jI       = d_in[4];                 // [M] int64 (or int32)
    float*       out      = (float*)d_out;           // [B, S, F] fp32

    k_convert<<<Mdim / 256, 256>>>(iI, jI);

    k_trans<<<dim3(Fdim / 64, 12 + BS / 64), 256>>>(up_dec, up_facts);

    k_rowptr<<<Mdim / 256, 256>>>();

    k_values<<<Fdim, 128>>>(down_enc);

    k_spmm<<<Fdim / SR, 256>>>(out);
}